// round 16
// baseline (speedup 1.0000x reference)
#include <cuda_runtime.h>
#include <math.h>

#define BB   512
#define LL   10000
#define NCH  100          // chunks per sequence
#define LCH  100          // chunk length (NCH*LCH == LL)
#define NLAY 4

typedef unsigned long long u64;

// ---------- f32x2 packed helpers (Blackwell sm_103a) ----------
__device__ __forceinline__ u64 pk(float lo, float hi) {
    u64 r; asm("mov.b64 %0,{%1,%2};" : "=l"(r) : "f"(lo), "f"(hi)); return r;
}
__device__ __forceinline__ void upk(u64 v, float& lo, float& hi) {
    asm("mov.b64 {%0,%1},%2;" : "=f"(lo), "=f"(hi) : "l"(v));
}
__device__ __forceinline__ u64 fma2(u64 a, u64 b, u64 c) {
    u64 d; asm("fma.rn.f32x2 %0,%1,%2,%3;" : "=l"(d) : "l"(a), "l"(b), "l"(c)); return d;
}
__device__ __forceinline__ u64 mul2(u64 a, u64 b) {
    u64 d; asm("mul.rn.f32x2 %0,%1,%2;" : "=l"(d) : "l"(a), "l"(b)); return d;
}
__device__ __forceinline__ u64 add2(u64 a, u64 b) {
    u64 d; asm("add.rn.f32x2 %0,%1,%2;" : "=l"(d) : "l"(a), "l"(b)); return d;
}

// ---------- scratch (static device globals: no allocation allowed) ----------
__device__ float  g_u[BB * 2 * LL];              // (B,H,L) activations (in place)
__device__ float2 g_E[BB * NCH * 2 * 32];        // chunk-end local states
__device__ float2 g_carry[BB * NCH * 2 * 32];    // chunk carry-in states
__device__ float2 g_lam[NLAY * 2 * 32];          // lambda (re,im)
__device__ float2 g_lam2[NLAY * 2 * 32];         // lambda^2 (re,im)
__device__ float2 g_cm[NLAY * 2 * 32];           // (2*Cn_re, -2*Cn_im)
__device__ float2 g_lamLc[NLAY * 2 * 32];        // lambda^LCH
__device__ float2 g_lamLc25[NLAY * 2 * 32];      // lambda^(25*LCH)

// ---------- setup: per-mode constants (fp64 for phase accuracy) ----------
__global__ void k_setup(const float* __restrict__ log_dt,
                        const float* __restrict__ log_A_real,
                        const float* __restrict__ A_imag,
                        const float* __restrict__ C) {
    int i = threadIdx.x;                 // 0..255 = NLAY*2*32
    int n = i & 31, h = (i >> 5) & 1, l = i >> 6;
    int hn = (l * 2 + h) * 32 + n;
    double dt  = exp((double)log_dt[l * 2 + h]);
    double Are = -exp((double)log_A_real[hn]);
    double Aim = (double)A_imag[hn];
    double dre = Are * dt, dim = Aim * dt;
    double er  = exp(dre);
    double lre = er * cos(dim), lim = er * sin(dim);
    double er2 = exp(dre * 2.0);
    double l2re = er2 * cos(dim * 2.0), l2im = er2 * sin(dim * 2.0);
    double erL = exp(dre * (double)LCH);
    double lLre = erL * cos(dim * (double)LCH);
    double lLim = erL * sin(dim * (double)LCH);
    double er25 = exp(dre * (double)(25 * LCH));
    double l25re = er25 * cos(dim * (double)(25 * LCH));
    double l25im = er25 * sin(dim * (double)(25 * LCH));
    double cr = (double)C[hn * 2 + 0], ci = (double)C[hn * 2 + 1];
    // Cn = Cc * (lambda - 1) / A
    double numr = lre - 1.0, numi = lim;
    double den = Are * Are + Aim * Aim;
    double qr = (numr * Are + numi * Aim) / den;
    double qi = (numi * Are - numr * Aim) / den;
    double cmr = 2.0 * (cr * qr - ci * qi);
    double cmi = 2.0 * (cr * qi + ci * qr);
    g_lam[hn]     = make_float2((float)lre, (float)lim);
    g_lam2[hn]    = make_float2((float)l2re, (float)l2im);
    g_cm[hn]      = make_float2((float)cmr, (float)(-cmi));   // imag pre-negated
    g_lamLc[hn]   = make_float2((float)lLre, (float)lLim);
    g_lamLc25[hn] = make_float2((float)l25re, (float)l25im);
}

// ---------- pass 1 (layer 0): single-step recurrence + fused W1 ----------
// Thread decode: bit0=h, bit1=half(mode group), rest=(b,chunk).
__global__ __launch_bounds__(128, 4) void k_pass1_first(const float* __restrict__ x,
                                                        const float* __restrict__ W1,
                                                        const float* __restrict__ b1) {
    int gid  = blockIdx.x * 128 + threadIdx.x;   // B*NCH*4 threads
    int h    = gid & 1;
    int half = (gid >> 1) & 1;
    int bc   = gid >> 2;
    int c    = bc % NCH;
    int b    = bc / NCH;
    const float2* lam = g_lam + h * 32 + half * 16;   // layer 0
    u64 lre[8], lim[8], nli[8], sre[8], sim[8];
#pragma unroll
    for (int p = 0; p < 8; p++) {
        float2 a0 = lam[2 * p], a1 = lam[2 * p + 1];
        lre[p] = pk(a0.x, a1.x);
        lim[p] = pk(a0.y, a1.y);
        nli[p] = pk(-a0.y, -a1.y);
        sre[p] = 0ULL;
        sim[p] = 0ULL;
    }
    float w0 = W1[h * 3 + 0], w1 = W1[h * 3 + 1], w2 = W1[h * 3 + 2], cb = b1[h];
    const float4* xp = (const float4*)(x + ((size_t)b * LL + c * LCH) * 3);
    float* ubase = g_u + (size_t)(b * 2 + h) * LL + c * LCH;

    float4 curX0 = __ldg(xp), curX1 = __ldg(xp + 1), curX2 = __ldg(xp + 2);
#pragma unroll 1
    for (int g = 0; g < LCH / 4; g++) {
        float4 nxtX0, nxtX1, nxtX2;
        if (g < LCH / 4 - 1) {
            nxtX0 = __ldg(xp + 3 * g + 3);
            nxtX1 = __ldg(xp + 3 * g + 4);
            nxtX2 = __ldg(xp + 3 * g + 5);
        }
        float us[4];
        us[0] = fmaf(w0, curX0.x, fmaf(w1, curX0.y, fmaf(w2, curX0.z, cb)));
        us[1] = fmaf(w0, curX0.w, fmaf(w1, curX1.x, fmaf(w2, curX1.y, cb)));
        us[2] = fmaf(w0, curX1.z, fmaf(w1, curX1.w, fmaf(w2, curX2.x, cb)));
        us[3] = fmaf(w0, curX2.y, fmaf(w1, curX2.z, fmaf(w2, curX2.w, cb)));
        if (half == 0)
            *((float4*)ubase + g) = make_float4(us[0], us[1], us[2], us[3]);
#pragma unroll
        for (int j = 0; j < 4; j++) {
            u64 ub = pk(us[j], us[j]);
#pragma unroll
            for (int p = 0; p < 8; p++) {
                u64 nr = fma2(nli[p], sim[p], fma2(lre[p], sre[p], ub));
                u64 ni = fma2(lim[p], sre[p], mul2(lre[p], sim[p]));
                sre[p] = nr;
                sim[p] = ni;
            }
        }
        curX0 = nxtX0; curX1 = nxtX1; curX2 = nxtX2;
    }
    float2* Ep = g_E + (size_t)((b * NCH + c) * 2 + h) * 32 + half * 16;
#pragma unroll
    for (int p = 0; p < 8; p++) {
        float r0, r1, i0, i1;
        upk(sre[p], r0, r1);
        upk(sim[p], i0, i1);
        Ep[2 * p]     = make_float2(r0, i0);
        Ep[2 * p + 1] = make_float2(r1, i1);
    }
}

// ---------- pass 2: block-parallel chunk scan -> carry-in per chunk ----------
// Block = (b,h); thread tid = cg*32 + n; cg in [0,4) handles 25 chunks of mode n.
__global__ __launch_bounds__(128) void k_scan(int layer) {
    int bi = blockIdx.x;                 // BB*2 blocks
    int h = bi & 1, b = bi >> 1;
    int tid = threadIdx.x;
    int n = tid & 31, cg = tid >> 5;
    __shared__ float2 sE[25][128];
    __shared__ float2 sT[128];
    float2 lamL  = g_lamLc[(layer * 2 + h) * 32 + n];
    float2 lam25 = g_lamLc25[(layer * 2 + h) * 32 + n];
    size_t base = ((size_t)(b * NCH) * 2 + h) * 32 + n;   // + c*64
    // phase 1: local inclusive scan of this group's 25 chunk end-states
    float2 v = make_float2(0.f, 0.f);
#pragma unroll 1
    for (int j = 0; j < 25; j++) {
        float2 e = __ldg(&g_E[base + (size_t)(cg * 25 + j) * 64]);
        sE[j][tid] = e;
        float nr = fmaf(lamL.x, v.x, fmaf(-lamL.y, v.y, e.x));
        float ni = fmaf(lamL.x, v.y, fmaf(lamL.y, v.x, e.y));
        v.x = nr; v.y = ni;
    }
    sT[tid] = v;
    __syncthreads();
    // phase 2: carry into first chunk of group cg: S = sum_{j<cg} lam25^{cg-1-j} T_j
    float2 S = make_float2(0.f, 0.f);
    for (int j = 0; j < cg; j++) {
        float2 T = sT[j * 32 + n];
        float nr = fmaf(lam25.x, S.x, fmaf(-lam25.y, S.y, T.x));
        float ni = fmaf(lam25.x, S.y, fmaf(lam25.y, S.x, T.y));
        S.x = nr; S.y = ni;
    }
    // phase 3: re-walk writing per-chunk carries
#pragma unroll 1
    for (int j = 0; j < 25; j++) {
        g_carry[base + (size_t)(cg * 25 + j) * 64] = S;
        float2 e = sE[j][tid];
        float nr = fmaf(lamL.x, S.x, fmaf(-lamL.y, S.y, e.x));
        float ni = fmaf(lamL.x, S.y, fmaf(lamL.y, S.x, e.y));
        S.x = nr; S.y = ni;
    }
}

// ---------- activation helpers ----------
__device__ __forceinline__ float gelu_f(float x) {
    return 0.5f * x * (1.f + erff(x * 0.70710678118654752f));
}
__device__ __forceinline__ float sig_f(float x) {
    return 1.f / (1.f + __expf(-x));
}

// ---------- fused MID layer: recurrence(l) -> epilogue -> u' -> pass1(l+1) ---
// Layers 0..2. Consumes g_carry(l); updates g_u in place; emits g_E for l+1
// via the 2-step-doubled local recurrence of layer l+1 run on un as produced.
__global__ __launch_bounds__(128, 2) void k_fused_mid(int layer,
                                                      const float* __restrict__ Dp,
                                                      const float* __restrict__ Wout,
                                                      const float* __restrict__ bout) {
    int gid  = blockIdx.x * 128 + threadIdx.x;   // B*NCH*4 threads
    int h    = gid & 1;
    int half = (gid >> 1) & 1;
    int bc   = gid >> 2;
    int c    = bc % NCH;
    int b    = bc / NCH;
    const float2* lam = g_lam + (layer * 2 + h) * 32 + half * 16;
    const float2* cmp = g_cm  + (layer * 2 + h) * 32 + half * 16;
    const float2* cyp = g_carry + (size_t)((b * NCH + c) * 2 + h) * 32 + half * 16;
    float Dh = __ldg(Dp + layer * 2 + h);
    const float* W  = Wout + layer * 8;   // (4 rows, 2 cols) row-major
    const float* bo = bout + layer * 4;
    int ho = 1 - h;
    float waS = W[h * 2 + h],       waO = W[h * 2 + ho],       ba = bo[h];
    float wgS = W[(2 + h) * 2 + h], wgO = W[(2 + h) * 2 + ho], bg = bo[2 + h];

    // layer-l constants + carry state
    u64 lre[8], lim[8], nli[8], cre[8], nci[8], sre[8], sim[8];
#pragma unroll
    for (int p = 0; p < 8; p++) {
        float2 a0 = lam[2 * p], a1 = lam[2 * p + 1];
        lre[p] = pk(a0.x, a1.x);
        lim[p] = pk(a0.y, a1.y);
        nli[p] = pk(-a0.y, -a1.y);
        float2 c0 = cmp[2 * p], c1 = cmp[2 * p + 1];
        cre[p] = pk(c0.x, c1.x);
        nci[p] = pk(c0.y, c1.y);                 // already negated imag
        float2 s0 = cyp[2 * p], s1 = cyp[2 * p + 1];
        sre[p] = pk(s0.x, s1.x);
        sim[p] = pk(s0.y, s1.y);
    }
    // layer-(l+1) doubled-recurrence constants + zero state
    const float2* Nlam  = g_lam  + ((layer + 1) * 2 + h) * 32 + half * 16;
    const float2* Nlam2 = g_lam2 + ((layer + 1) * 2 + h) * 32 + half * 16;
    u64 Alre[8], Anli[8], A2re[8], A2im[8], A2ni[8], tre[8], tms[8];
#pragma unroll
    for (int p = 0; p < 8; p++) {
        float2 a0 = Nlam[2 * p],  a1 = Nlam[2 * p + 1];
        float2 q0 = Nlam2[2 * p], q1 = Nlam2[2 * p + 1];
        Alre[p] = pk(a0.x, a1.x);
        Anli[p] = pk(-a0.y, -a1.y);
        A2re[p] = pk(q0.x, q1.x);
        A2im[p] = pk(q0.y, q1.y);
        A2ni[p] = pk(-q0.y, -q1.y);
        tre[p] = 0ULL;
        tms[p] = 0ULL;
    }
    float* ubase = g_u + (size_t)(b * 2 + h) * LL + c * LCH;

    float4 cur = __ldg((const float4*)ubase);
    float4 nx1 = __ldg((const float4*)ubase + 1);
#pragma unroll 1
    for (int g = 0; g < LCH / 4; g++) {
        float4 nx2;
        if (g + 2 < LCH / 4) nx2 = __ldg((const float4*)ubase + g + 2);
        const float us[4] = {cur.x, cur.y, cur.z, cur.w};
        float yp[4];
#pragma unroll
        for (int j = 0; j < 4; j++) {
            u64 ub = pk(us[j], us[j]);
            u64 a0 = 0ULL, a1 = 0ULL;
#pragma unroll
            for (int p = 0; p < 8; p++) {
                u64 nr = fma2(nli[p], sim[p], fma2(lre[p], sre[p], ub));
                u64 ni = fma2(lim[p], sre[p], mul2(lre[p], sim[p]));
                sre[p] = nr;
                sim[p] = ni;
                a0 = fma2(cre[p], nr, a0);
                a1 = fma2(nci[p], ni, a1);
            }
            u64 s = add2(a0, a1);
            float flo, fhi;
            upk(s, flo, fhi);
            yp[j] = flo + fhi;                       // this thread's 16 modes
        }
        // ---- round A: publish-partner half-combine (2 shuffles) ----
        int jb = 2 * half;
        float pub0 = half ? yp[0] : yp[2];
        float pub1 = half ? yp[1] : yp[3];
        float rc0 = __shfl_xor_sync(0xFFFFFFFFu, pub0, 2);
        float rc1 = __shfl_xor_sync(0xFFFFFFFFu, pub1, 2);
        // ---- work-split GELU (this lane's 2 timesteps) ----
        float gw2[2];
        gw2[0] = gelu_f(fmaf(Dh, us[jb + 0], yp[jb + 0] + rc0));
        gw2[1] = gelu_f(fmaf(Dh, us[jb + 1], yp[jb + 1] + rc1));
        // ---- round B: cross-channel (2 shuffles) ----
        float go2[2];
        go2[0] = __shfl_xor_sync(0xFFFFFFFFu, gw2[0], 1);
        go2[1] = __shfl_xor_sync(0xFFFFFFFFu, gw2[1], 1);
        // ---- GLU ----
        float un2[2];
#pragma unroll
        for (int k = 0; k < 2; k++) {
            float za = fmaf(waS, gw2[k], fmaf(waO, go2[k], ba));
            float zg = fmaf(wgS, gw2[k], fmaf(wgO, go2[k], bg));
            un2[k] = za * sig_f(zg);
        }
        // ---- per-half float2 store of u' ----
        *(float2*)(ubase + g * 4 + 2 * half) = make_float2(un2[0], un2[1]);
        // ---- round C: regather full un[0..3] for next-layer recurrence ----
        float unx0 = __shfl_xor_sync(0xFFFFFFFFu, un2[0], 2);
        float unx1 = __shfl_xor_sync(0xFFFFFFFFu, un2[1], 2);
        float un0 = half ? unx0 : un2[0];
        float un1 = half ? unx1 : un2[1];
        float un2f = half ? un2[0] : unx0;
        float un3 = half ? un2[1] : unx1;
        // ---- layer-(l+1) doubled local recurrence on un[0..3] ----
        {
            u64 u0b = pk(un0, un0), u1b = pk(un1, un1);
            u64 u2b = pk(un2f, un2f), u3b = pk(un3, un3);
#pragma unroll
            for (int p = 0; p < 8; p++) {
                u64 wre = fma2(Alre[p], u0b, u1b);
                u64 mw  = mul2(Anli[p], u0b);
                u64 nr  = fma2(A2im[p], tms[p], fma2(A2re[p], tre[p], wre));
                u64 nm  = fma2(A2ni[p], tre[p], fma2(A2re[p], tms[p], mw));
                u64 wre2 = fma2(Alre[p], u2b, u3b);
                u64 mw2  = mul2(Anli[p], u2b);
                tre[p] = fma2(A2im[p], nm, fma2(A2re[p], nr, wre2));
                tms[p] = fma2(A2ni[p], nr, fma2(A2re[p], nm, mw2));
            }
        }
        cur = nx1;
        nx1 = nx2;
    }
    // emit E for layer l+1
    float2* Ep = g_E + (size_t)((b * NCH + c) * 2 + h) * 32 + half * 16;
#pragma unroll
    for (int p = 0; p < 8; p++) {
        float r0, r1, m0, m1;
        upk(tre[p], r0, r1);
        upk(tms[p], m0, m1);
        Ep[2 * p]     = make_float2(r0, -m0);
        Ep[2 * p + 1] = make_float2(r1, -m1);
    }
}

// ---------- fused LAST layer: recurrence -> epilogue -> W2 -> out ----------
__global__ __launch_bounds__(128, 3) void k_fused_last(int layer,
                                                       const float* __restrict__ Dp,
                                                       const float* __restrict__ Wout,
                                                       const float* __restrict__ bout,
                                                       const float* __restrict__ W2,
                                                       const float* __restrict__ b2,
                                                       float* __restrict__ out) {
    int gid  = blockIdx.x * 128 + threadIdx.x;   // B*NCH*4 threads
    int h    = gid & 1;
    int half = (gid >> 1) & 1;
    int bc   = gid >> 2;
    int c    = bc % NCH;
    int b    = bc / NCH;
    const float2* lam = g_lam + (layer * 2 + h) * 32 + half * 16;
    const float2* cmp = g_cm  + (layer * 2 + h) * 32 + half * 16;
    const float2* cyp = g_carry + (size_t)((b * NCH + c) * 2 + h) * 32 + half * 16;
    float Dh = __ldg(Dp + layer * 2 + h);
    const float* W  = Wout + layer * 8;
    const float* bo = bout + layer * 4;
    int ho = 1 - h;
    float waS = W[h * 2 + h],       waO = W[h * 2 + ho],       ba = bo[h];
    float wgS = W[(2 + h) * 2 + h], wgO = W[(2 + h) * 2 + ho], bg = bo[2 + h];
    float w200 = W2[0], w201 = W2[1], b20 = b2[0];
    float w210 = W2[2], w211 = W2[3], b21 = b2[1];

    u64 lre[8], lim[8], nli[8], cre[8], nci[8], sre[8], sim[8];
#pragma unroll
    for (int p = 0; p < 8; p++) {
        float2 a0 = lam[2 * p], a1 = lam[2 * p + 1];
        lre[p] = pk(a0.x, a1.x);
        lim[p] = pk(a0.y, a1.y);
        nli[p] = pk(-a0.y, -a1.y);
        float2 c0 = cmp[2 * p], c1 = cmp[2 * p + 1];
        cre[p] = pk(c0.x, c1.x);
        nci[p] = pk(c0.y, c1.y);
        float2 s0 = cyp[2 * p], s1 = cyp[2 * p + 1];
        sre[p] = pk(s0.x, s1.x);
        sim[p] = pk(s0.y, s1.y);
    }
    const float* ubase = g_u + (size_t)(b * 2 + h) * LL + c * LCH;
    float* obase = out + ((size_t)b * LL + c * LCH) * 2;

    float4 cur = __ldg((const float4*)ubase);
    float4 nx1 = __ldg((const float4*)ubase + 1);
#pragma unroll 1
    for (int g = 0; g < LCH / 4; g++) {
        float4 nx2;
        if (g + 2 < LCH / 4) nx2 = __ldg((const float4*)ubase + g + 2);
        const float us[4] = {cur.x, cur.y, cur.z, cur.w};
        float yp[4];
#pragma unroll
        for (int j = 0; j < 4; j++) {
            u64 ub = pk(us[j], us[j]);
            u64 a0 = 0ULL, a1 = 0ULL;
#pragma unroll
            for (int p = 0; p < 8; p++) {
                u64 nr = fma2(nli[p], sim[p], fma2(lre[p], sre[p], ub));
                u64 ni = fma2(lim[p], sre[p], mul2(lre[p], sim[p]));
                sre[p] = nr;
                sim[p] = ni;
                a0 = fma2(cre[p], nr, a0);
                a1 = fma2(nci[p], ni, a1);
            }
            u64 s = add2(a0, a1);
            float flo, fhi;
            upk(s, flo, fhi);
            yp[j] = flo + fhi;
        }
        // ---- round A: publish-partner half-combine (2 shuffles) ----
        int jb = 2 * half;
        float pub0 = half ? yp[0] : yp[2];
        float pub1 = half ? yp[1] : yp[3];
        float rc0 = __shfl_xor_sync(0xFFFFFFFFu, pub0, 2);
        float rc1 = __shfl_xor_sync(0xFFFFFFFFu, pub1, 2);
        // ---- work-split GELU ----
        float gw2[2];
        gw2[0] = gelu_f(fmaf(Dh, us[jb + 0], yp[jb + 0] + rc0));
        gw2[1] = gelu_f(fmaf(Dh, us[jb + 1], yp[jb + 1] + rc1));
        // ---- round B: cross-channel (2 shuffles) ----
        float go2[2];
        go2[0] = __shfl_xor_sync(0xFFFFFFFFu, gw2[0], 1);
        go2[1] = __shfl_xor_sync(0xFFFFFFFFu, gw2[1], 1);
        // ---- GLU ----
        float un2[2];
#pragma unroll
        for (int k = 0; k < 2; k++) {
            float za = fmaf(waS, gw2[k], fmaf(waO, go2[k], ba));
            float zg = fmaf(wgS, gw2[k], fmaf(wgO, go2[k], bg));
            un2[k] = za * sig_f(zg);
        }
        // ---- exchange channels for this lane's 2 timesteps, apply W2 ----
        float uo2[2];
        uo2[0] = __shfl_xor_sync(0xFFFFFFFFu, un2[0], 1);
        uo2[1] = __shfl_xor_sync(0xFFFFFFFFu, un2[1], 1);
        float u0a = h ? uo2[0] : un2[0];
        float u1a = h ? un2[0] : uo2[0];
        float u0b = h ? uo2[1] : un2[1];
        float u1b = h ? un2[1] : uo2[1];
        float4 O;
        O.x = fmaf(w200, u0a, fmaf(w201, u1a, b20));
        O.y = fmaf(w210, u0a, fmaf(w211, u1a, b21));
        O.z = fmaf(w200, u0b, fmaf(w201, u1b, b20));
        O.w = fmaf(w210, u0b, fmaf(w211, u1b, b21));
        if (h == 0)
            *(float4*)(obase + (g * 4 + 2 * half) * 2) = O;
        cur = nx1;
        nx1 = nx2;
    }
}

extern "C" void kernel_launch(void* const* d_in, const int* in_sizes, int n_in,
                              void* d_out, int out_size) {
    (void)in_sizes; (void)n_in; (void)out_size;
    const float* x          = (const float*)d_in[0];
    const float* W1         = (const float*)d_in[1];
    const float* b1         = (const float*)d_in[2];
    const float* W2         = (const float*)d_in[3];
    const float* b2         = (const float*)d_in[4];
    const float* log_dt     = (const float*)d_in[5];
    const float* log_A_real = (const float*)d_in[6];
    const float* A_imag     = (const float*)d_in[7];
    const float* C          = (const float*)d_in[8];
    const float* D          = (const float*)d_in[9];
    const float* Wout       = (const float*)d_in[10];
    const float* bout       = (const float*)d_in[11];
    float* out = (float*)d_out;

    const int g14 = (BB * NCH * 4) / 128;    // 1600 blocks (half-split kernels)
    const int gsc = BB * 2;                  // 1024 blocks

    k_setup<<<1, NLAY * 2 * 32>>>(log_dt, log_A_real, A_imag, C);
    k_pass1_first<<<g14, 128>>>(x, W1, b1);           // E(layer 0)
    for (int l = 0; l < NLAY; l++) {
        k_scan<<<gsc, 128>>>(l);                      // carries(l) from E(l)
        if (l < NLAY - 1)
            k_fused_mid<<<g14, 128>>>(l, D, Wout, bout);   // u' + E(l+1)
        else
            k_fused_last<<<g14, 128>>>(l, D, Wout, bout, W2, b2, out);
    }
}

// round 17
// speedup vs baseline: 1.6709x; 1.6709x over previous
#include <cuda_runtime.h>
#include <math.h>

#define BB   512
#define LL   10000
#define NCH  100          // chunks per sequence
#define LCH  100          // chunk length (NCH*LCH == LL)
#define NLAY 4

typedef unsigned long long u64;

// ---------- f32x2 packed helpers (Blackwell sm_103a) ----------
__device__ __forceinline__ u64 pk(float lo, float hi) {
    u64 r; asm("mov.b64 %0,{%1,%2};" : "=l"(r) : "f"(lo), "f"(hi)); return r;
}
__device__ __forceinline__ void upk(u64 v, float& lo, float& hi) {
    asm("mov.b64 {%0,%1},%2;" : "=f"(lo), "=f"(hi) : "l"(v));
}
__device__ __forceinline__ u64 fma2(u64 a, u64 b, u64 c) {
    u64 d; asm("fma.rn.f32x2 %0,%1,%2,%3;" : "=l"(d) : "l"(a), "l"(b), "l"(c)); return d;
}
__device__ __forceinline__ u64 mul2(u64 a, u64 b) {
    u64 d; asm("mul.rn.f32x2 %0,%1,%2;" : "=l"(d) : "l"(a), "l"(b)); return d;
}
__device__ __forceinline__ u64 add2(u64 a, u64 b) {
    u64 d; asm("add.rn.f32x2 %0,%1,%2;" : "=l"(d) : "l"(a), "l"(b)); return d;
}

// ---------- scratch (static device globals: no allocation allowed) ----------
__device__ float  g_u[BB * 2 * LL];              // (B,H,L) activations (in place)
__device__ float2 g_E[BB * NCH * 2 * 32];        // chunk-end local states
__device__ float2 g_carry[BB * NCH * 2 * 32];    // chunk carry-in states
__device__ float2 g_lam[NLAY * 2 * 32];          // lambda (re,im)
__device__ float2 g_lam2[NLAY * 2 * 32];         // lambda^2 (re,im)
__device__ float2 g_cm[NLAY * 2 * 32];           // (2*Cn_re, -2*Cn_im)
__device__ float2 g_lamLc[NLAY * 2 * 32];        // lambda^LCH
__device__ float2 g_lamLc25[NLAY * 2 * 32];      // lambda^(25*LCH)

// ---------- setup: per-mode constants (fp64 for phase accuracy) ----------
__global__ void k_setup(const float* __restrict__ log_dt,
                        const float* __restrict__ log_A_real,
                        const float* __restrict__ A_imag,
                        const float* __restrict__ C) {
    int i = threadIdx.x;                 // 0..255 = NLAY*2*32
    int n = i & 31, h = (i >> 5) & 1, l = i >> 6;
    int hn = (l * 2 + h) * 32 + n;
    double dt  = exp((double)log_dt[l * 2 + h]);
    double Are = -exp((double)log_A_real[hn]);
    double Aim = (double)A_imag[hn];
    double dre = Are * dt, dim = Aim * dt;
    double er  = exp(dre);
    double lre = er * cos(dim), lim = er * sin(dim);
    double er2 = exp(dre * 2.0);
    double l2re = er2 * cos(dim * 2.0), l2im = er2 * sin(dim * 2.0);
    double erL = exp(dre * (double)LCH);
    double lLre = erL * cos(dim * (double)LCH);
    double lLim = erL * sin(dim * (double)LCH);
    double er25 = exp(dre * (double)(25 * LCH));
    double l25re = er25 * cos(dim * (double)(25 * LCH));
    double l25im = er25 * sin(dim * (double)(25 * LCH));
    double cr = (double)C[hn * 2 + 0], ci = (double)C[hn * 2 + 1];
    // Cn = Cc * (lambda - 1) / A
    double numr = lre - 1.0, numi = lim;
    double den = Are * Are + Aim * Aim;
    double qr = (numr * Are + numi * Aim) / den;
    double qi = (numi * Are - numr * Aim) / den;
    double cmr = 2.0 * (cr * qr - ci * qi);
    double cmi = 2.0 * (cr * qi + ci * qr);
    g_lam[hn]     = make_float2((float)lre, (float)lim);
    g_lam2[hn]    = make_float2((float)l2re, (float)l2im);
    g_cm[hn]      = make_float2((float)cmr, (float)(-cmi));   // imag pre-negated
    g_lamLc[hn]   = make_float2((float)lLre, (float)lLim);
    g_lamLc25[hn] = make_float2((float)l25re, (float)l25im);
}

// ---------- pass 1 (layer 0): single-step recurrence + fused W1 ----------
// Thread decode: bit0=h, bit1=half(mode group), rest=(b,chunk).
__global__ __launch_bounds__(128, 4) void k_pass1_first(const float* __restrict__ x,
                                                        const float* __restrict__ W1,
                                                        const float* __restrict__ b1) {
    int gid  = blockIdx.x * 128 + threadIdx.x;   // B*NCH*4 threads
    int h    = gid & 1;
    int half = (gid >> 1) & 1;
    int bc   = gid >> 2;
    int c    = bc % NCH;
    int b    = bc / NCH;
    const float2* lam = g_lam + h * 32 + half * 16;   // layer 0
    u64 lre[8], lim[8], nli[8], sre[8], sim[8];
#pragma unroll
    for (int p = 0; p < 8; p++) {
        float2 a0 = lam[2 * p], a1 = lam[2 * p + 1];
        lre[p] = pk(a0.x, a1.x);
        lim[p] = pk(a0.y, a1.y);
        nli[p] = pk(-a0.y, -a1.y);
        sre[p] = 0ULL;
        sim[p] = 0ULL;
    }
    float w0 = W1[h * 3 + 0], w1 = W1[h * 3 + 1], w2 = W1[h * 3 + 2], cb = b1[h];
    const float4* xp = (const float4*)(x + ((size_t)b * LL + c * LCH) * 3);
    float* ubase = g_u + (size_t)(b * 2 + h) * LL + c * LCH;

    float4 curX0 = __ldg(xp), curX1 = __ldg(xp + 1), curX2 = __ldg(xp + 2);
#pragma unroll 1
    for (int g = 0; g < LCH / 4; g++) {
        float4 nxtX0, nxtX1, nxtX2;
        if (g < LCH / 4 - 1) {
            nxtX0 = __ldg(xp + 3 * g + 3);
            nxtX1 = __ldg(xp + 3 * g + 4);
            nxtX2 = __ldg(xp + 3 * g + 5);
        }
        float us[4];
        us[0] = fmaf(w0, curX0.x, fmaf(w1, curX0.y, fmaf(w2, curX0.z, cb)));
        us[1] = fmaf(w0, curX0.w, fmaf(w1, curX1.x, fmaf(w2, curX1.y, cb)));
        us[2] = fmaf(w0, curX1.z, fmaf(w1, curX1.w, fmaf(w2, curX2.x, cb)));
        us[3] = fmaf(w0, curX2.y, fmaf(w1, curX2.z, fmaf(w2, curX2.w, cb)));
        if (half == 0)
            *((float4*)ubase + g) = make_float4(us[0], us[1], us[2], us[3]);
#pragma unroll
        for (int j = 0; j < 4; j++) {
            u64 ub = pk(us[j], us[j]);
#pragma unroll
            for (int p = 0; p < 8; p++) {
                u64 nr = fma2(nli[p], sim[p], fma2(lre[p], sre[p], ub));
                u64 ni = fma2(lim[p], sre[p], mul2(lre[p], sim[p]));
                sre[p] = nr;
                sim[p] = ni;
            }
        }
        curX0 = nxtX0; curX1 = nxtX1; curX2 = nxtX2;
    }
    float2* Ep = g_E + (size_t)((b * NCH + c) * 2 + h) * 32 + half * 16;
#pragma unroll
    for (int p = 0; p < 8; p++) {
        float r0, r1, i0, i1;
        upk(sre[p], r0, r1);
        upk(sim[p], i0, i1);
        Ep[2 * p]     = make_float2(r0, i0);
        Ep[2 * p + 1] = make_float2(r1, i1);
    }
}

// ---------- pass 1 (layers 1..3): 2-step-doubled recurrence (prefetch-1) -----
// s'' = lam^2 * s + lam*u0 + u1, state (sre, ms=-sim): 6 packed ops / 2 steps.
__global__ __launch_bounds__(128, 4) void k_pass1_dbl(int layer) {
    int gid  = blockIdx.x * 128 + threadIdx.x;   // B*NCH*4 threads
    int h    = gid & 1;
    int half = (gid >> 1) & 1;
    int bc   = gid >> 2;
    int c    = bc % NCH;
    int b    = bc / NCH;
    const float2* lam  = g_lam  + (layer * 2 + h) * 32 + half * 16;
    const float2* lam2 = g_lam2 + (layer * 2 + h) * 32 + half * 16;
    u64 lre[8], nli[8], l2re[8], l2im[8], nl2i[8], sre[8], ms[8];
#pragma unroll
    for (int p = 0; p < 8; p++) {
        float2 a0 = lam[2 * p],  a1 = lam[2 * p + 1];
        float2 q0 = lam2[2 * p], q1 = lam2[2 * p + 1];
        lre[p]  = pk(a0.x, a1.x);
        nli[p]  = pk(-a0.y, -a1.y);
        l2re[p] = pk(q0.x, q1.x);
        l2im[p] = pk(q0.y, q1.y);
        nl2i[p] = pk(-q0.y, -q1.y);
        sre[p] = 0ULL;
        ms[p]  = 0ULL;
    }
    const float* ubase = g_u + (size_t)(b * 2 + h) * LL + c * LCH;
    float4 cur = __ldg((const float4*)ubase);
#pragma unroll 1
    for (int g = 0; g < LCH / 4; g++) {
        float4 nxt;
        if (g < LCH / 4 - 1) nxt = __ldg((const float4*)ubase + g + 1);
        u64 u0b = pk(cur.x, cur.x), u1b = pk(cur.y, cur.y);
        u64 u2b = pk(cur.z, cur.z), u3b = pk(cur.w, cur.w);
#pragma unroll
        for (int p = 0; p < 8; p++) {
            // steps t, t+1
            u64 wre = fma2(lre[p], u0b, u1b);
            u64 mw  = mul2(nli[p], u0b);
            u64 nr  = fma2(l2im[p], ms[p], fma2(l2re[p], sre[p], wre));
            u64 nm  = fma2(nl2i[p], sre[p], fma2(l2re[p], ms[p], mw));
            // steps t+2, t+3
            u64 wre2 = fma2(lre[p], u2b, u3b);
            u64 mw2  = mul2(nli[p], u2b);
            sre[p] = fma2(l2im[p], nm, fma2(l2re[p], nr, wre2));
            ms[p]  = fma2(nl2i[p], nr, fma2(l2re[p], nm, mw2));
        }
        cur = nxt;
    }
    float2* Ep = g_E + (size_t)((b * NCH + c) * 2 + h) * 32 + half * 16;
#pragma unroll
    for (int p = 0; p < 8; p++) {
        float r0, r1, m0, m1;
        upk(sre[p], r0, r1);
        upk(ms[p], m0, m1);
        Ep[2 * p]     = make_float2(r0, -m0);
        Ep[2 * p + 1] = make_float2(r1, -m1);
    }
}

// ---------- pass 2: block-parallel chunk scan -> carry-in per chunk ----------
// Block = (b,h); thread tid = cg*32 + n; cg in [0,4) handles 25 chunks of mode n.
__global__ __launch_bounds__(128) void k_scan(int layer) {
    int bi = blockIdx.x;                 // BB*2 blocks
    int h = bi & 1, b = bi >> 1;
    int tid = threadIdx.x;
    int n = tid & 31, cg = tid >> 5;
    __shared__ float2 sE[25][128];
    __shared__ float2 sT[128];
    float2 lamL  = g_lamLc[(layer * 2 + h) * 32 + n];
    float2 lam25 = g_lamLc25[(layer * 2 + h) * 32 + n];
    size_t base = ((size_t)(b * NCH) * 2 + h) * 32 + n;   // + c*64
    // phase 1: local inclusive scan of this group's 25 chunk end-states
    float2 v = make_float2(0.f, 0.f);
#pragma unroll 1
    for (int j = 0; j < 25; j++) {
        float2 e = __ldg(&g_E[base + (size_t)(cg * 25 + j) * 64]);
        sE[j][tid] = e;
        float nr = fmaf(lamL.x, v.x, fmaf(-lamL.y, v.y, e.x));
        float ni = fmaf(lamL.x, v.y, fmaf(lamL.y, v.x, e.y));
        v.x = nr; v.y = ni;
    }
    sT[tid] = v;
    __syncthreads();
    // phase 2: carry into first chunk of group cg: S = sum_{j<cg} lam25^{cg-1-j} T_j
    float2 S = make_float2(0.f, 0.f);
    for (int j = 0; j < cg; j++) {
        float2 T = sT[j * 32 + n];
        float nr = fmaf(lam25.x, S.x, fmaf(-lam25.y, S.y, T.x));
        float ni = fmaf(lam25.x, S.y, fmaf(lam25.y, S.x, T.y));
        S.x = nr; S.y = ni;
    }
    // phase 3: re-walk writing per-chunk carries
#pragma unroll 1
    for (int j = 0; j < 25; j++) {
        g_carry[base + (size_t)(cg * 25 + j) * 64] = S;
        float2 e = sE[j][tid];
        float nr = fmaf(lamL.x, S.x, fmaf(-lamL.y, S.y, e.x));
        float ni = fmaf(lamL.x, S.y, fmaf(lamL.y, S.x, e.y));
        S.x = nr; S.y = ni;
    }
}

// ---------- activation helpers ----------
__device__ __forceinline__ float gelu_f(float x) {
    return 0.5f * x * (1.f + erff(x * 0.70710678118654752f));
}
__device__ __forceinline__ float sig_f(float x) {
    return 1.f / (1.f + __expf(-x));
}

// ---------- fused pass 3+4 (non-last): recurrence -> GELU -> Wout -> GLU -----
// R14 form: half-split, work-split epilogue, publish-partner round A (2 shfl),
// per-half float2 stores (round C eliminated), prefetch depth 2.
__global__ __launch_bounds__(128, 3) void k_fused3(int layer,
                                                   const float* __restrict__ Dp,
                                                   const float* __restrict__ Wout,
                                                   const float* __restrict__ bout) {
    int gid  = blockIdx.x * 128 + threadIdx.x;   // B*NCH*4 threads
    int h    = gid & 1;
    int half = (gid >> 1) & 1;
    int bc   = gid >> 2;
    int c    = bc % NCH;
    int b    = bc / NCH;
    const float2* lam = g_lam + (layer * 2 + h) * 32 + half * 16;
    const float2* cmp = g_cm  + (layer * 2 + h) * 32 + half * 16;
    const float2* cyp = g_carry + (size_t)((b * NCH + c) * 2 + h) * 32 + half * 16;
    float Dh = __ldg(Dp + layer * 2 + h);
    const float* W  = Wout + layer * 8;   // (4 rows, 2 cols) row-major
    const float* bo = bout + layer * 4;
    int ho = 1 - h;
    float waS = W[h * 2 + h],       waO = W[h * 2 + ho],       ba = bo[h];
    float wgS = W[(2 + h) * 2 + h], wgO = W[(2 + h) * 2 + ho], bg = bo[2 + h];
    u64 lre[8], lim[8], nli[8], cre[8], nci[8], sre[8], sim[8];
#pragma unroll
    for (int p = 0; p < 8; p++) {
        float2 a0 = lam[2 * p], a1 = lam[2 * p + 1];
        lre[p] = pk(a0.x, a1.x);
        lim[p] = pk(a0.y, a1.y);
        nli[p] = pk(-a0.y, -a1.y);
        float2 c0 = cmp[2 * p], c1 = cmp[2 * p + 1];
        cre[p] = pk(c0.x, c1.x);
        nci[p] = pk(c0.y, c1.y);                 // already negated imag
        float2 s0 = cyp[2 * p], s1 = cyp[2 * p + 1];
        sre[p] = pk(s0.x, s1.x);
        sim[p] = pk(s0.y, s1.y);
    }
    float* ubase = g_u + (size_t)(b * 2 + h) * LL + c * LCH;

    float4 cur = __ldg((const float4*)ubase);
    float4 nx1 = __ldg((const float4*)ubase + 1);
#pragma unroll 1
    for (int g = 0; g < LCH / 4; g++) {
        float4 nx2;
        if (g + 2 < LCH / 4) nx2 = __ldg((const float4*)ubase + g + 2);
        const float us[4] = {cur.x, cur.y, cur.z, cur.w};
        float yp[4];
#pragma unroll
        for (int j = 0; j < 4; j++) {
            u64 ub = pk(us[j], us[j]);
            u64 a0 = 0ULL, a1 = 0ULL;
#pragma unroll
            for (int p = 0; p < 8; p++) {
                u64 nr = fma2(nli[p], sim[p], fma2(lre[p], sre[p], ub));
                u64 ni = fma2(lim[p], sre[p], mul2(lre[p], sim[p]));
                sre[p] = nr;
                sim[p] = ni;
                a0 = fma2(cre[p], nr, a0);
                a1 = fma2(nci[p], ni, a1);
            }
            u64 s = add2(a0, a1);
            float flo, fhi;
            upk(s, flo, fhi);
            yp[j] = flo + fhi;                       // this thread's 16 modes
        }
        // ---- round A: publish-partner half-combine (2 shuffles) ----
        int jb = 2 * half;
        float pub0 = half ? yp[0] : yp[2];
        float pub1 = half ? yp[1] : yp[3];
        float rc0 = __shfl_xor_sync(0xFFFFFFFFu, pub0, 2);
        float rc1 = __shfl_xor_sync(0xFFFFFFFFu, pub1, 2);
        // ---- work-split GELU (this lane's 2 timesteps) ----
        float gw2[2];
        gw2[0] = gelu_f(fmaf(Dh, us[jb + 0], yp[jb + 0] + rc0));
        gw2[1] = gelu_f(fmaf(Dh, us[jb + 1], yp[jb + 1] + rc1));
        // ---- round B: cross-channel (2 shuffles) ----
        float go2[2];
        go2[0] = __shfl_xor_sync(0xFFFFFFFFu, gw2[0], 1);
        go2[1] = __shfl_xor_sync(0xFFFFFFFFu, gw2[1], 1);
        // ---- GLU ----
        float un2[2];
#pragma unroll
        for (int k = 0; k < 2; k++) {
            float za = fmaf(waS, gw2[k], fmaf(waO, go2[k], ba));
            float zg = fmaf(wgS, gw2[k], fmaf(wgO, go2[k], bg));
            un2[k] = za * sig_f(zg);
        }
        // ---- per-half float2 store (round C eliminated) ----
        *(float2*)(ubase + g * 4 + 2 * half) = make_float2(un2[0], un2[1]);
        cur = nx1;
        nx1 = nx2;
    }
}

// ---------- fused LAST layer: recurrence -> epilogue -> W2 -> out ----------
// R15-verified work-split output path (6 shuffles/group).
__global__ __launch_bounds__(128, 3) void k_fused_last(int layer,
                                                       const float* __restrict__ Dp,
                                                       const float* __restrict__ Wout,
                                                       const float* __restrict__ bout,
                                                       const float* __restrict__ W2,
                                                       const float* __restrict__ b2,
                                                       float* __restrict__ out) {
    int gid  = blockIdx.x * 128 + threadIdx.x;   // B*NCH*4 threads
    int h    = gid & 1;
    int half = (gid >> 1) & 1;
    int bc   = gid >> 2;
    int c    = bc % NCH;
    int b    = bc / NCH;
    const float2* lam = g_lam + (layer * 2 + h) * 32 + half * 16;
    const float2* cmp = g_cm  + (layer * 2 + h) * 32 + half * 16;
    const float2* cyp = g_carry + (size_t)((b * NCH + c) * 2 + h) * 32 + half * 16;
    float Dh = __ldg(Dp + layer * 2 + h);
    const float* W  = Wout + layer * 8;
    const float* bo = bout + layer * 4;
    int ho = 1 - h;
    float waS = W[h * 2 + h],       waO = W[h * 2 + ho],       ba = bo[h];
    float wgS = W[(2 + h) * 2 + h], wgO = W[(2 + h) * 2 + ho], bg = bo[2 + h];
    float w200 = W2[0], w201 = W2[1], b20 = b2[0];
    float w210 = W2[2], w211 = W2[3], b21 = b2[1];

    u64 lre[8], lim[8], nli[8], cre[8], nci[8], sre[8], sim[8];
#pragma unroll
    for (int p = 0; p < 8; p++) {
        float2 a0 = lam[2 * p], a1 = lam[2 * p + 1];
        lre[p] = pk(a0.x, a1.x);
        lim[p] = pk(a0.y, a1.y);
        nli[p] = pk(-a0.y, -a1.y);
        float2 c0 = cmp[2 * p], c1 = cmp[2 * p + 1];
        cre[p] = pk(c0.x, c1.x);
        nci[p] = pk(c0.y, c1.y);
        float2 s0 = cyp[2 * p], s1 = cyp[2 * p + 1];
        sre[p] = pk(s0.x, s1.x);
        sim[p] = pk(s0.y, s1.y);
    }
    const float* ubase = g_u + (size_t)(b * 2 + h) * LL + c * LCH;
    float* obase = out + ((size_t)b * LL + c * LCH) * 2;

    float4 cur = __ldg((const float4*)ubase);
    float4 nx1 = __ldg((const float4*)ubase + 1);
#pragma unroll 1
    for (int g = 0; g < LCH / 4; g++) {
        float4 nx2;
        if (g + 2 < LCH / 4) nx2 = __ldg((const float4*)ubase + g + 2);
        const float us[4] = {cur.x, cur.y, cur.z, cur.w};
        float yp[4];
#pragma unroll
        for (int j = 0; j < 4; j++) {
            u64 ub = pk(us[j], us[j]);
            u64 a0 = 0ULL, a1 = 0ULL;
#pragma unroll
            for (int p = 0; p < 8; p++) {
                u64 nr = fma2(nli[p], sim[p], fma2(lre[p], sre[p], ub));
                u64 ni = fma2(lim[p], sre[p], mul2(lre[p], sim[p]));
                sre[p] = nr;
                sim[p] = ni;
                a0 = fma2(cre[p], nr, a0);
                a1 = fma2(nci[p], ni, a1);
            }
            u64 s = add2(a0, a1);
            float flo, fhi;
            upk(s, flo, fhi);
            yp[j] = flo + fhi;
        }
        // ---- round A: publish-partner half-combine (2 shuffles) ----
        int jb = 2 * half;
        float pub0 = half ? yp[0] : yp[2];
        float pub1 = half ? yp[1] : yp[3];
        float rc0 = __shfl_xor_sync(0xFFFFFFFFu, pub0, 2);
        float rc1 = __shfl_xor_sync(0xFFFFFFFFu, pub1, 2);
        // ---- work-split GELU ----
        float gw2[2];
        gw2[0] = gelu_f(fmaf(Dh, us[jb + 0], yp[jb + 0] + rc0));
        gw2[1] = gelu_f(fmaf(Dh, us[jb + 1], yp[jb + 1] + rc1));
        // ---- round B: cross-channel (2 shuffles) ----
        float go2[2];
        go2[0] = __shfl_xor_sync(0xFFFFFFFFu, gw2[0], 1);
        go2[1] = __shfl_xor_sync(0xFFFFFFFFu, gw2[1], 1);
        // ---- GLU ----
        float un2[2];
#pragma unroll
        for (int k = 0; k < 2; k++) {
            float za = fmaf(waS, gw2[k], fmaf(waO, go2[k], ba));
            float zg = fmaf(wgS, gw2[k], fmaf(wgO, go2[k], bg));
            un2[k] = za * sig_f(zg);
        }
        // ---- exchange channels for this lane's 2 timesteps, apply W2 ----
        float uo2[2];
        uo2[0] = __shfl_xor_sync(0xFFFFFFFFu, un2[0], 1);
        uo2[1] = __shfl_xor_sync(0xFFFFFFFFu, un2[1], 1);
        float u0a = h ? uo2[0] : un2[0];
        float u1a = h ? un2[0] : uo2[0];
        float u0b = h ? uo2[1] : un2[1];
        float u1b = h ? un2[1] : uo2[1];
        float4 O;
        O.x = fmaf(w200, u0a, fmaf(w201, u1a, b20));
        O.y = fmaf(w210, u0a, fmaf(w211, u1a, b21));
        O.z = fmaf(w200, u0b, fmaf(w201, u1b, b20));
        O.w = fmaf(w210, u0b, fmaf(w211, u1b, b21));
        if (h == 0)
            *(float4*)(obase + (g * 4 + 2 * half) * 2) = O;
        cur = nx1;
        nx1 = nx2;
    }
}

extern "C" void kernel_launch(void* const* d_in, const int* in_sizes, int n_in,
                              void* d_out, int out_size) {
    (void)in_sizes; (void)n_in; (void)out_size;
    const float* x          = (const float*)d_in[0];
    const float* W1         = (const float*)d_in[1];
    const float* b1         = (const float*)d_in[2];
    const float* W2         = (const float*)d_in[3];
    const float* b2         = (const float*)d_in[4];
    const float* log_dt     = (const float*)d_in[5];
    const float* log_A_real = (const float*)d_in[6];
    const float* A_imag     = (const float*)d_in[7];
    const float* C          = (const float*)d_in[8];
    const float* D          = (const float*)d_in[9];
    const float* Wout       = (const float*)d_in[10];
    const float* bout       = (const float*)d_in[11];
    float* out = (float*)d_out;

    const int g14 = (BB * NCH * 4) / 128;    // 1600 blocks (half-split kernels)
    const int gsc = BB * 2;                  // 1024 blocks

    k_setup<<<1, NLAY * 2 * 32>>>(log_dt, log_A_real, A_imag, C);
    for (int l = 0; l < NLAY; l++) {
        if (l == 0) k_pass1_first<<<g14, 128>>>(x, W1, b1);
        else        k_pass1_dbl<<<g14, 128>>>(l);
        k_scan<<<gsc, 128>>>(l);
        if (l == NLAY - 1)
            k_fused_last<<<g14, 128>>>(l, D, Wout, bout, W2, b2, out);
        else
            k_fused3<<<g14, 128>>>(l, D, Wout, bout);
    }
}